// round 16
// baseline (speedup 1.0000x reference)
#include <cuda_runtime.h>
#include <cuda.h>
#include <math.h>
#include <stdint.h>

// YOLO loss: preds [16384,7,7,30] f32, labels same, scalar f32 out.
// R16: deep cp.async.bulk DMA ring to maximize in-flight bytes.
//   148 blocks (1 CTA/SM) x 128 threads; 6272 chunks of 128 cells.
//   7 stages x 30720 B = 215040 B smem/CTA -> ~27 MB in flight chip-wide.
//   Thread 0 issues 2 bulk copies + expect_tx per stage; acquire parity wait
//   (parity = ring-pass count & 1); __syncthreads before refill.
//   Block reduce + ticket atomic; last block reduces 148 partials in double.

#define SIDE 7
#define NBATCH 16384
#define NTHREADS 128
#define TILE_CELLS 128
#define NUM_CHUNKS 6272            // 802816 / 128 exactly
#define PGRID 148                  // 1 CTA per SM
#define FLOATS_PER_CELL 30
#define TILEF (TILE_CELLS * FLOATS_PER_CELL)   // 3840 floats
#define TILE_BYTES (TILEF * 4)                 // 15360 B per array
#define STAGE_BYTES (2 * TILE_BYTES)           // 30720 B
#define NSTAGES 7
#define SMEM_BYTES (NSTAGES * STAGE_BYTES)     // 215040 B dynamic

__device__ float g_partials[PGRID];
__device__ unsigned int g_ticket = 0;

__device__ __forceinline__ void mbar_init(uint32_t mbar, uint32_t count) {
    asm volatile("mbarrier.init.shared.b64 [%0], %1;"
                 :: "r"(mbar), "r"(count) : "memory");
}
__device__ __forceinline__ void mbar_expect_tx(uint32_t mbar, uint32_t tx) {
    asm volatile("mbarrier.arrive.expect_tx.shared.b64 _, [%0], %1;"
                 :: "r"(mbar), "r"(tx) : "memory");
}
__device__ __forceinline__ void mbar_wait_acq(uint32_t mbar, uint32_t parity) {
    uint32_t done;
    asm volatile(
        "{\n\t.reg .pred p;\n\t"
        "mbarrier.try_wait.parity.acquire.cta.shared::cta.b64 p, [%1], %2;\n\t"
        "selp.b32 %0, 1, 0, p;\n\t}"
        : "=r"(done) : "r"(mbar), "r"(parity) : "memory");
    while (!done) {
        asm volatile(
            "{\n\t.reg .pred p;\n\t"
            "mbarrier.try_wait.parity.acquire.cta.shared::cta.b64 p, [%1], %2, 0x989680;\n\t"
            "selp.b32 %0, 1, 0, p;\n\t}"
            : "=r"(done) : "r"(mbar), "r"(parity) : "memory");
    }
}
__device__ __forceinline__ void bulk_cp(uint32_t sdst, const void* gsrc,
                                        uint32_t bytes, uint32_t mbar) {
    asm volatile(
        "cp.async.bulk.shared::cluster.global.mbarrier::complete_tx::bytes "
        "[%0], [%1], %2, [%3];"
        :: "r"(sdst), "l"(gsrc), "r"(bytes), "r"(mbar) : "memory");
}
__device__ __forceinline__ void fence_async() {
    asm volatile("fence.proxy.async.shared::cta;" ::: "memory");
}

// Issue one 128-cell chunk (15360 B preds + 15360 B labels) into a stage.
__device__ __forceinline__ void issue_chunk(uint32_t stage_base, uint32_t mbar,
                                            const char* preds, const char* labels,
                                            int chunk)
{
    const long long off = (long long)chunk * TILE_BYTES;
    mbar_expect_tx(mbar, STAGE_BYTES);
    bulk_cp(stage_base, preds + off, TILE_BYTES, mbar);
    bulk_cp(stage_base + TILE_BYTES, labels + off, TILE_BYTES, mbar);
}

// Proven scalar cell loss (R4/R10/R11/R14/R15).
__device__ __forceinline__ float cell_loss(const float* __restrict__ p,
                                           const float* __restrict__ l)
{
    const float s = 1.0f / (float)SIDE;
    float conf = l[4];
    if (conf == 0.0f) {
        float d0 = p[4] - l[4];
        float d1 = p[9] - l[9];
        return 0.5f * (d0 * d0 + d1 * d1);
    }
    float l1x = l[0] * s - 0.5f * l[2];
    float l1y = l[1] * s - 0.5f * l[3];
    float l2x = l[0] * s + 0.5f * l[2];
    float l2y = l[1] * s + 0.5f * l[3];
    float la  = l[2] * l[3];

    float iou0, iou1;
    #pragma unroll
    for (int b = 0; b < 2; b++) {
        const float* pb = p + b * 5;
        float p1x = pb[0] * s - 0.5f * pb[2];
        float p1y = pb[1] * s - 0.5f * pb[3];
        float p2x = pb[0] * s + 0.5f * pb[2];
        float p2y = pb[1] * s + 0.5f * pb[3];
        float iw = fmaxf(fminf(p2x, l2x) - fmaxf(p1x, l1x), 0.0f);
        float ih = fmaxf(fminf(p2y, l2y) - fmaxf(p1y, l1y), 0.0f);
        float inter = iw * ih;
        float pa = pb[2] * pb[3];
        float v = inter / (pa + la - inter);
        if (b == 0) iou0 = v; else iou1 = v;
    }

    int idx = (iou1 > iou0) ? 1 : 0;   // jnp.argmax: first max wins
    float maxiou = fmaxf(iou0, iou1);

    const float* pr = p + idx * 5;
    const float* lr = l + idx * 5;

    float dresp = pr[4] - maxiou;
    float resp  = dresp * dresp;

    float nrc = p[(1 - idx) * 5 + 4];
    float nr  = nrc * nrc;

    float dx = pr[0] - lr[0];
    float dy = pr[1] - lr[1];
    float xy = dx * dx + dy * dy;

    float dw = sqrtf(pr[2]) - sqrtf(lr[2]);
    float dh = sqrtf(pr[3]) - sqrtf(lr[3]);
    float wh = dw * dw + dh * dh;

    float cls = 0.0f;
    #pragma unroll
    for (int k = 10; k < 30; k++) {
        float d = p[k] - l[k];
        cls += d * d;
    }

    return 5.0f * (xy + wh) + 2.0f * resp + nr + cls;
}

extern __shared__ char smem[];   // [7 stages][preds 15360 | labels 15360]

__global__ __launch_bounds__(NTHREADS)
void yolo_deep_ring_kernel(const float* __restrict__ preds,
                           const float* __restrict__ labels,
                           float* __restrict__ out)
{
    const int t = threadIdx.x;
    const char* pc = (const char*)preds;
    const char* lc = (const char*)labels;

    __shared__ uint64_t mbar_store[NSTAGES];
    const uint32_t mbar_base = (uint32_t)__cvta_generic_to_shared(mbar_store);
    const uint32_t sbase = (uint32_t)__cvta_generic_to_shared(smem);

    if (t == 0) {
        #pragma unroll
        for (int i = 0; i < NSTAGES; i++)
            mbar_init(mbar_base + 8u * i, 1);
        fence_async();
    }
    __syncthreads();

    const int c0 = blockIdx.x;

    // Prologue: fill all 7 stages (every block has >= 42 chunks, so all valid).
    if (t == 0) {
        #pragma unroll
        for (int k = 0; k < NSTAGES; k++) {
            int c = c0 + k * PGRID;
            if (c < NUM_CHUNKS)
                issue_chunk(sbase + (uint32_t)k * STAGE_BYTES,
                            mbar_base + 8u * k, pc, lc, c);
        }
    }

    float acc_cell = 0.0f;
    int stage = 0;
    uint32_t pass = 0;   // parity for stage s on its v-th visit = v & 1

    #pragma unroll 1
    for (int c = c0; c < NUM_CHUNKS; c += PGRID) {
        uint32_t mb = mbar_base + 8u * stage;
        mbar_wait_acq(mb, pass & 1u);

        {
            const float* sp = (const float*)(smem + (size_t)stage * STAGE_BYTES);
            const float* sl = sp + TILEF;
            acc_cell += cell_loss(sp + t * FLOATS_PER_CELL,
                                  sl + t * FLOATS_PER_CELL);
        }
        __syncthreads();   // all generic reads done before DMA refills stage

        int cf = c + NSTAGES * PGRID;
        if (cf < NUM_CHUNKS && t == 0)
            issue_chunk(sbase + (uint32_t)stage * STAGE_BYTES, mb, pc, lc, cf);

        stage++;
        if (stage == NSTAGES) { stage = 0; pass ^= 1u; }
    }

    // Block reduction: warp shuffle tree then cross-warp via smem.
    float v = acc_cell;
    #pragma unroll
    for (int off = 16; off > 0; off >>= 1)
        v += __shfl_down_sync(0xFFFFFFFFu, v, off);

    __shared__ float wsum[NTHREADS / 32];
    int lane = t & 31;
    int wid  = t >> 5;
    if (lane == 0) wsum[wid] = v;
    __syncthreads();

    __shared__ bool is_last;
    if (t == 0) {
        float bacc = 0.0f;
        #pragma unroll
        for (int w = 0; w < NTHREADS / 32; w++) bacc += wsum[w];
        g_partials[blockIdx.x] = bacc;
        __threadfence();
        unsigned int ticket = atomicAdd(&g_ticket, 1u);
        is_last = (ticket == PGRID - 1);
    }
    __syncthreads();

    // Last-arriving block: deterministic final reduction over 148 partials.
    if (is_last) {
        double acc = 0.0;
        #pragma unroll 1
        for (int i = t; i < PGRID; i += NTHREADS)
            acc += (double)g_partials[i];

        #pragma unroll
        for (int off = 16; off > 0; off >>= 1)
            acc += __shfl_down_sync(0xFFFFFFFFu, acc, off);

        __shared__ double dsum[NTHREADS / 32];
        if (lane == 0) dsum[wid] = acc;
        __syncthreads();

        if (t == 0) {
            double total = 0.0;
            #pragma unroll
            for (int w = 0; w < NTHREADS / 32; w++) total += dsum[w];
            out[0] = (float)(total / (double)NBATCH);
            g_ticket = 0;   // reset for next graph replay
        }
    }
}

extern "C" void kernel_launch(void* const* d_in, const int* in_sizes, int n_in,
                              void* d_out, int out_size)
{
    const float* preds  = (const float*)d_in[0];
    const float* labels = (const float*)d_in[1];
    float* out = (float*)d_out;

    static bool attr_set = false;
    if (!attr_set) {
        cudaFuncSetAttribute(yolo_deep_ring_kernel,
                             cudaFuncAttributeMaxDynamicSharedMemorySize,
                             SMEM_BYTES);
        attr_set = true;
    }

    yolo_deep_ring_kernel<<<PGRID, NTHREADS, SMEM_BYTES>>>(preds, labels, out);
}

// round 17
// speedup vs baseline: 1.0260x; 1.0260x over previous
#include <cuda_runtime.h>
#include <cuda.h>
#include <math.h>
#include <stdint.h>

// YOLO loss: preds [16384,7,7,30] f32, labels same, scalar f32 out.
// R17 = R14 (best kernel: block-level cp.async.bulk 3-stage ring) with a
// perfectly balanced grid: 448 blocks x 28 chunks of 64 cells each (exact).
//   Stage = 15360 B (7680 preds + 7680 labels); 3 stages = 46080 B smem.
//   Single wave (448 <= 592 resident at 4 CTAs/SM). Thread 0 issues 2 bulk
//   copies + expect_tx per stage; acquire parity wait; __syncthreads before
//   refill. Block reduce + ticket atomic; last block reduces 448 partials.

#define SIDE 7
#define NBATCH 16384
#define NTHREADS 128
#define TILE_CELLS 64
#define NUM_CHUNKS 12544           // 802816 / 64 exactly
#define PGRID 448                  // 12544 / 448 = 28 chunks/block exactly
#define FLOATS_PER_CELL 30
#define TILEF (TILE_CELLS * FLOATS_PER_CELL)   // 1920 floats
#define TILE_BYTES (TILEF * 4)                 // 7680 B per array
#define STAGE_BYTES (2 * TILE_BYTES)           // 15360 B
#define NSTAGES 3
#define SMEM_BYTES (NSTAGES * STAGE_BYTES)     // 46080 B dynamic

__device__ float g_partials[PGRID];
__device__ unsigned int g_ticket = 0;

__device__ __forceinline__ void mbar_init(uint32_t mbar, uint32_t count) {
    asm volatile("mbarrier.init.shared.b64 [%0], %1;"
                 :: "r"(mbar), "r"(count) : "memory");
}
__device__ __forceinline__ void mbar_expect_tx(uint32_t mbar, uint32_t tx) {
    asm volatile("mbarrier.arrive.expect_tx.shared.b64 _, [%0], %1;"
                 :: "r"(mbar), "r"(tx) : "memory");
}
__device__ __forceinline__ void mbar_wait_acq(uint32_t mbar, uint32_t parity) {
    uint32_t done;
    asm volatile(
        "{\n\t.reg .pred p;\n\t"
        "mbarrier.try_wait.parity.acquire.cta.shared::cta.b64 p, [%1], %2;\n\t"
        "selp.b32 %0, 1, 0, p;\n\t}"
        : "=r"(done) : "r"(mbar), "r"(parity) : "memory");
    while (!done) {
        asm volatile(
            "{\n\t.reg .pred p;\n\t"
            "mbarrier.try_wait.parity.acquire.cta.shared::cta.b64 p, [%1], %2, 0x989680;\n\t"
            "selp.b32 %0, 1, 0, p;\n\t}"
            : "=r"(done) : "r"(mbar), "r"(parity) : "memory");
    }
}
__device__ __forceinline__ void bulk_cp(uint32_t sdst, const void* gsrc,
                                        uint32_t bytes, uint32_t mbar) {
    asm volatile(
        "cp.async.bulk.shared::cluster.global.mbarrier::complete_tx::bytes "
        "[%0], [%1], %2, [%3];"
        :: "r"(sdst), "l"(gsrc), "r"(bytes), "r"(mbar) : "memory");
}
__device__ __forceinline__ void fence_async() {
    asm volatile("fence.proxy.async.shared::cta;" ::: "memory");
}

// Issue one 64-cell chunk (7680 B preds + 7680 B labels) into a stage.
__device__ __forceinline__ void issue_chunk(uint32_t stage_base, uint32_t mbar,
                                            const char* preds, const char* labels,
                                            int chunk)
{
    const long long off = (long long)chunk * TILE_BYTES;
    mbar_expect_tx(mbar, STAGE_BYTES);
    bulk_cp(stage_base, preds + off, TILE_BYTES, mbar);
    bulk_cp(stage_base + TILE_BYTES, labels + off, TILE_BYTES, mbar);
}

// Proven scalar cell loss (R4/R10/R11/R14/R15/R16).
__device__ __forceinline__ float cell_loss(const float* __restrict__ p,
                                           const float* __restrict__ l)
{
    const float s = 1.0f / (float)SIDE;
    float conf = l[4];
    if (conf == 0.0f) {
        float d0 = p[4] - l[4];
        float d1 = p[9] - l[9];
        return 0.5f * (d0 * d0 + d1 * d1);
    }
    float l1x = l[0] * s - 0.5f * l[2];
    float l1y = l[1] * s - 0.5f * l[3];
    float l2x = l[0] * s + 0.5f * l[2];
    float l2y = l[1] * s + 0.5f * l[3];
    float la  = l[2] * l[3];

    float iou0, iou1;
    #pragma unroll
    for (int b = 0; b < 2; b++) {
        const float* pb = p + b * 5;
        float p1x = pb[0] * s - 0.5f * pb[2];
        float p1y = pb[1] * s - 0.5f * pb[3];
        float p2x = pb[0] * s + 0.5f * pb[2];
        float p2y = pb[1] * s + 0.5f * pb[3];
        float iw = fmaxf(fminf(p2x, l2x) - fmaxf(p1x, l1x), 0.0f);
        float ih = fmaxf(fminf(p2y, l2y) - fmaxf(p1y, l1y), 0.0f);
        float inter = iw * ih;
        float pa = pb[2] * pb[3];
        float v = inter / (pa + la - inter);
        if (b == 0) iou0 = v; else iou1 = v;
    }

    int idx = (iou1 > iou0) ? 1 : 0;   // jnp.argmax: first max wins
    float maxiou = fmaxf(iou0, iou1);

    const float* pr = p + idx * 5;
    const float* lr = l + idx * 5;

    float dresp = pr[4] - maxiou;
    float resp  = dresp * dresp;

    float nrc = p[(1 - idx) * 5 + 4];
    float nr  = nrc * nrc;

    float dx = pr[0] - lr[0];
    float dy = pr[1] - lr[1];
    float xy = dx * dx + dy * dy;

    float dw = sqrtf(pr[2]) - sqrtf(lr[2]);
    float dh = sqrtf(pr[3]) - sqrtf(lr[3]);
    float wh = dw * dw + dh * dh;

    float cls = 0.0f;
    #pragma unroll
    for (int k = 10; k < 30; k++) {
        float d = p[k] - l[k];
        cls += d * d;
    }

    return 5.0f * (xy + wh) + 2.0f * resp + nr + cls;
}

extern __shared__ char smem[];   // [3 stages][preds 7680 | labels 7680]

__global__ __launch_bounds__(NTHREADS)
void yolo_dma448_kernel(const float* __restrict__ preds,
                        const float* __restrict__ labels,
                        float* __restrict__ out)
{
    const int t = threadIdx.x;
    const char* pc = (const char*)preds;
    const char* lc = (const char*)labels;

    __shared__ uint64_t mbar_store[NSTAGES];
    const uint32_t mbar_base = (uint32_t)__cvta_generic_to_shared(mbar_store);
    const uint32_t sbase = (uint32_t)__cvta_generic_to_shared(smem);

    if (t == 0) {
        #pragma unroll
        for (int i = 0; i < NSTAGES; i++)
            mbar_init(mbar_base + 8u * i, 1);
        fence_async();
    }
    __syncthreads();

    const int c0 = blockIdx.x;

    // Prologue: fill all three stages (28 chunks/block >= 3, all valid).
    if (t == 0) {
        #pragma unroll
        for (int k = 0; k < NSTAGES; k++)
            issue_chunk(sbase + (uint32_t)k * STAGE_BYTES,
                        mbar_base + 8u * k, pc, lc, c0 + k * PGRID);
    }

    float acc_cell = 0.0f;
    uint32_t phase0 = 0, phase1 = 0, phase2 = 0;

    int stage = 0;
    #pragma unroll 1
    for (int c = c0; c < NUM_CHUNKS; c += PGRID) {
        uint32_t mb = mbar_base + 8u * stage;
        if (stage == 0)      { mbar_wait_acq(mb, phase0); phase0 ^= 1u; }
        else if (stage == 1) { mbar_wait_acq(mb, phase1); phase1 ^= 1u; }
        else                 { mbar_wait_acq(mb, phase2); phase2 ^= 1u; }

        if (t < TILE_CELLS) {
            const float* sp = (const float*)(smem + (size_t)stage * STAGE_BYTES);
            const float* sl = sp + TILEF;
            acc_cell += cell_loss(sp + t * FLOATS_PER_CELL,
                                  sl + t * FLOATS_PER_CELL);
        }
        __syncthreads();   // all generic reads done before DMA refills stage

        int cf = c + NSTAGES * PGRID;
        if (cf < NUM_CHUNKS && t == 0)
            issue_chunk(sbase + (uint32_t)stage * STAGE_BYTES, mb, pc, lc, cf);

        stage++; if (stage >= NSTAGES) stage = 0;
    }

    // Block reduction: warp shuffle tree then cross-warp via smem.
    float v = acc_cell;
    #pragma unroll
    for (int off = 16; off > 0; off >>= 1)
        v += __shfl_down_sync(0xFFFFFFFFu, v, off);

    __shared__ float wsum[NTHREADS / 32];
    int lane = t & 31;
    int wid  = t >> 5;
    if (lane == 0) wsum[wid] = v;
    __syncthreads();

    __shared__ bool is_last;
    if (t == 0) {
        float bacc = 0.0f;
        #pragma unroll
        for (int w = 0; w < NTHREADS / 32; w++) bacc += wsum[w];
        g_partials[blockIdx.x] = bacc;
        __threadfence();
        unsigned int ticket = atomicAdd(&g_ticket, 1u);
        is_last = (ticket == PGRID - 1);
    }
    __syncthreads();

    // Last-arriving block: deterministic final reduction over 448 partials.
    if (is_last) {
        double acc = 0.0;
        #pragma unroll 1
        for (int i = t; i < PGRID; i += NTHREADS)
            acc += (double)g_partials[i];

        #pragma unroll
        for (int off = 16; off > 0; off >>= 1)
            acc += __shfl_down_sync(0xFFFFFFFFu, acc, off);

        __shared__ double dsum[NTHREADS / 32];
        if (lane == 0) dsum[wid] = acc;
        __syncthreads();

        if (t == 0) {
            double total = 0.0;
            #pragma unroll
            for (int w = 0; w < NTHREADS / 32; w++) total += dsum[w];
            out[0] = (float)(total / (double)NBATCH);
            g_ticket = 0;   // reset for next graph replay
        }
    }
}

extern "C" void kernel_launch(void* const* d_in, const int* in_sizes, int n_in,
                              void* d_out, int out_size)
{
    const float* preds  = (const float*)d_in[0];
    const float* labels = (const float*)d_in[1];
    float* out = (float*)d_out;

    static bool attr_set = false;
    if (!attr_set) {
        cudaFuncSetAttribute(yolo_dma448_kernel,
                             cudaFuncAttributeMaxDynamicSharedMemorySize,
                             SMEM_BYTES);
        attr_set = true;
    }

    yolo_dma448_kernel<<<PGRID, NTHREADS, SMEM_BYTES>>>(preds, labels, out);
}